// round 17
// baseline (speedup 1.0000x reference)
#include <cuda_runtime.h>
#include <cuda_bf16.h>
#include <cstdint>

#define N_RAYS 32768
#define M_G    1024
#define NTILES (M_G / 8)       // 128 n-tiles of 8 gaussians
#define HALF_TILES (NTILES / 2)        // 64
#define HALF_ROUNDS (HALF_TILES / 2)   // 32 rounds of 2 tiles
#define WARPS  4
#define RAYS_PER_WARP 32
#define RAYS_PER_BLOCK (WARPS * RAYS_PER_WARP)   // 128
#define NGROUPS (N_RAYS / RAYS_PER_BLOCK)        // 256 ray-groups

typedef unsigned int u32;

// B fragment table, tf32, m16n8k8 lane layout:
//   g_tblB[t*32 + lane] = float4{ w[tig], w[tig+4], w[tig+8], w[tig+12] }
__device__ __align__(16) float4 g_tblB[NTILES * 32];   // 64 KB
// Permuted labels (per 2-tile round r, tig)
__device__ __align__(16) float g_plab[M_G];
// Cross-block combine scratch + per-group counters (zero-init, self-resetting)
__device__ float g_part[2 * N_RAYS];
__device__ int   g_cnt[NGROUPS];

__device__ __forceinline__ float to_tf32(float x) {
    float r;
    asm("cvt.rna.tf32.f32 %0, %1;" : "=f"(r) : "f"(x));
    return r;
}

// ---------------------------------------------------------------------------
// Prep: invert Sigma (fp32 GJ + one Newton step), fold -0.5*log2(e) and mean
// into 16 coefficients, tf32-round, emit B fragments + permuted labels.
// ---------------------------------------------------------------------------
__global__ void prep_kernel(const float* __restrict__ means,
                            const float* __restrict__ covs,
                            const float* __restrict__ labels) {
    int m = blockIdx.x * blockDim.x + threadIdx.x;
    if (m >= M_G) return;

    float S[4][4], a[4][8];
    #pragma unroll
    for (int i = 0; i < 4; i++)
        #pragma unroll
        for (int j = 0; j < 4; j++) {
            S[i][j] = covs[m * 16 + i * 4 + j];
            a[i][j] = S[i][j];
        }
    #pragma unroll
    for (int i = 0; i < 4; i++)
        #pragma unroll
        for (int j = 0; j < 4; j++) a[i][4 + j] = (i == j) ? 1.0f : 0.0f;
    #pragma unroll
    for (int c = 0; c < 4; c++) {
        float inv = __frcp_rn(a[c][c]);
        #pragma unroll
        for (int j = 0; j < 8; j++) a[c][j] *= inv;
        #pragma unroll
        for (int r = 0; r < 4; r++) {
            if (r == c) continue;
            float f = a[r][c];
            #pragma unroll
            for (int j = 0; j < 8; j++) a[r][j] = fmaf(-f, a[c][j], a[r][j]);
        }
    }
    float X[4][4], T[4][4], Xr[4][4];
    #pragma unroll
    for (int i = 0; i < 4; i++)
        #pragma unroll
        for (int j = 0; j < 4; j++) X[i][j] = a[i][4 + j];
    #pragma unroll
    for (int i = 0; i < 4; i++)
        #pragma unroll
        for (int j = 0; j < 4; j++) {
            float s = (i == j) ? 2.0f : 0.0f;
            #pragma unroll
            for (int k = 0; k < 4; k++) s = fmaf(-S[i][k], X[k][j], s);
            T[i][j] = s;
        }
    #pragma unroll
    for (int i = 0; i < 4; i++)
        #pragma unroll
        for (int j = 0; j < 4; j++) {
            float s = 0.0f;
            #pragma unroll
            for (int k = 0; k < 4; k++) s = fmaf(X[i][k], T[k][j], s);
            Xr[i][j] = s;
        }
    const float kk = -0.5f * 1.4426950408889634f;   // -0.5*log2(e)
    float C[4][4];
    #pragma unroll
    for (int i = 0; i < 4; i++)
        #pragma unroll
        for (int j = 0; j < 4; j++) C[i][j] = kk * Xr[i][j];
    float mu[4];
    #pragma unroll
    for (int i = 0; i < 4; i++) mu[i] = means[m * 4 + i];

    float w[16];
    w[0] = C[0][0]; w[1] = C[1][1]; w[2] = C[2][2]; w[3] = C[3][3];
    w[4] = 2.0f * C[0][1]; w[5] = 2.0f * C[0][2]; w[6] = 2.0f * C[0][3];
    w[7] = 2.0f * C[1][2]; w[8] = 2.0f * C[1][3]; w[9] = 2.0f * C[2][3];
    #pragma unroll
    for (int i = 0; i < 4; i++) {
        float s = 0.0f;
        #pragma unroll
        for (int j = 0; j < 4; j++) s = fmaf(C[i][j], mu[j], s);
        w[10 + i] = -2.0f * s;
    }
    float q = 0.0f;
    #pragma unroll
    for (int i = 0; i < 4; i++) {
        float s = 0.0f;
        #pragma unroll
        for (int j = 0; j < 4; j++) s = fmaf(C[i][j], mu[j], s);
        q = fmaf(mu[i], s, q);
    }
    w[14] = q;
    w[15] = 0.0f;

    #pragma unroll
    for (int k = 0; k < 16; k++) w[k] = to_tf32(w[k]);

    const int t = m >> 3, j = m & 7;
    #pragma unroll
    for (int tg = 0; tg < 4; tg++) {
        g_tblB[t * 32 + 4 * j + tg] =
            make_float4(w[tg], w[tg + 4], w[tg + 8], w[tg + 12]);
    }
    {
        const int r = t >> 1, odd = t & 1, tg = j >> 1, p = j & 1;
        g_plab[r * 16 + tg * 4 + odd * 2 + p] = labels[m];
    }
}

// ---------------------------------------------------------------------------
// Decoder: 512 blocks = 256 ray-groups x 2 gaussian-halves; 128 threads =
// 4 warps x 32 rays (two m16 row-groups/warp, B fragments reused 2x).
// 32 rounds of 2 tiles; epilogue inline (TLP hides latency at 4 CTA/SM).
// Second-arriving half combines partials + sigmoid (threadfence reduction).
// ---------------------------------------------------------------------------
#define SM_TBL   0
#define SM_LAB   (HALF_TILES * 32 * 16)              // 32768
#define SM_STAGE (SM_LAB + (M_G / 2) * 4)            // 34816
#define STAGE_W  17
#define SM_FLAG  (SM_STAGE + RAYS_PER_BLOCK * STAGE_W * 4)  // 43520
#define SM_TOTAL (SM_FLAG + 16)

extern __shared__ unsigned char smem_raw[];

__device__ __forceinline__ void mma_tf32(float& c0, float& c1, float& c2, float& c3,
                                         u32 a0, u32 a1, u32 a2, u32 a3,
                                         u32 b0, u32 b1) {
    asm volatile(
        "mma.sync.aligned.m16n8k8.row.col.f32.tf32.tf32.f32 "
        "{%0,%1,%2,%3}, {%4,%5,%6,%7}, {%8,%9}, {%0,%1,%2,%3};"
        : "+f"(c0), "+f"(c1), "+f"(c2), "+f"(c3)
        : "r"(a0), "r"(a1), "r"(a2), "r"(a3), "r"(b0), "r"(b1));
}

#define EPI4(P, La, Lb, aA, aB, aC, aD)                                         \
    {                                                                           \
        float e;                                                                \
        asm("ex2.approx.ftz.f32 %0, %1;" : "=f"(e) : "f"((P)[0]));              \
        aA = fmaf(La, e, aA);                                                   \
        asm("ex2.approx.ftz.f32 %0, %1;" : "=f"(e) : "f"((P)[1]));              \
        aB = fmaf(Lb, e, aB);                                                   \
        asm("ex2.approx.ftz.f32 %0, %1;" : "=f"(e) : "f"((P)[2]));              \
        aC = fmaf(La, e, aC);                                                   \
        asm("ex2.approx.ftz.f32 %0, %1;" : "=f"(e) : "f"((P)[3]));              \
        aD = fmaf(Lb, e, aD);                                                   \
    }

__global__ void __launch_bounds__(128, 4)
decoder_kernel(const float* __restrict__ origins,
               const float* __restrict__ dirs,
               float* __restrict__ out) {
    const int tid  = threadIdx.x;
    const int wid  = tid >> 5;
    const int lane = tid & 31;
    const int gid  = lane >> 2;
    const int tig  = lane & 3;
    const int rg   = blockIdx.x >> 1;   // ray group
    const int hf   = blockIdx.x & 1;    // gaussian half

    // ---- A staging FIRST (independent of prep -> overlaps under PDL) ----
    u32* stage = reinterpret_cast<u32*>(smem_raw + SM_STAGE) +
                 wid * RAYS_PER_WARP * STAGE_W;
    const int ray_base = rg * RAYS_PER_BLOCK + wid * RAYS_PER_WARP;
    {
        const int n = ray_base + lane;
        const float2 o = reinterpret_cast<const float2*>(origins)[n];
        const float2 d = reinterpret_cast<const float2*>(dirs)[n];
        const float p0 = o.x, p1 = o.y, p2 = d.x, p3 = d.y;
        float phi[16];
        phi[0] = p0 * p0; phi[1] = p1 * p1; phi[2] = p2 * p2; phi[3] = p3 * p3;
        phi[4] = p0 * p1; phi[5] = p0 * p2; phi[6] = p0 * p3;
        phi[7] = p1 * p2; phi[8] = p1 * p3; phi[9] = p2 * p3;
        phi[10] = p0; phi[11] = p1; phi[12] = p2; phi[13] = p3;
        phi[14] = 1.0f; phi[15] = 0.0f;
        u32* row = stage + lane * STAGE_W;
        #pragma unroll
        for (int k = 0; k < 16; k++)
            row[k] = __float_as_uint(to_tf32(phi[k]));
    }

    // ---- PDL gate ----
    asm volatile("griddepcontrol.wait;" ::: "memory");

    // ---- cooperative copies: half table (32KB) + half labels (2KB) ----
    {
        const uint4* gt = reinterpret_cast<const uint4*>(g_tblB + hf * (HALF_TILES * 32));
        uint4* st = reinterpret_cast<uint4*>(smem_raw + SM_TBL);
        #pragma unroll
        for (int i = 0; i < (HALF_TILES * 32 * 16 / 16) / 128; i++)
            st[tid + i * 128] = gt[tid + i * 128];
        const uint4* gl = reinterpret_cast<const uint4*>(g_plab + hf * (M_G / 2));
        uint4* sl = reinterpret_cast<uint4*>(smem_raw + SM_LAB);
        sl[tid] = gl[tid];   // 512 floats = 128 uint4
    }
    __syncthreads();

    // ---- load A fragments: [kstep][ray-group][frag] ----
    u32 afr[2][2][4];
    #pragma unroll
    for (int s = 0; s < 2; s++)
        #pragma unroll
        for (int g = 0; g < 2; g++) {
            const int r0 = g * 16 + gid, r1 = g * 16 + gid + 8;
            afr[s][g][0] = stage[r0 * STAGE_W + 8 * s + tig];
            afr[s][g][1] = stage[r1 * STAGE_W + 8 * s + tig];
            afr[s][g][2] = stage[r0 * STAGE_W + 8 * s + tig + 4];
            afr[s][g][3] = stage[r1 * STAGE_W + 8 * s + tig + 4];
        }

    const float4* tbl = reinterpret_cast<const float4*>(smem_raw + SM_TBL);
    const float4* lab4 = reinterpret_cast<const float4*>(smem_raw + SM_LAB);

    float aA0 = 0.f, aA1 = 0.f, aA2 = 0.f, aA3 = 0.f;   // ray-group 0
    float aB0 = 0.f, aB1 = 0.f, aB2 = 0.f, aB3 = 0.f;   // ray-group 1

    #pragma unroll 2
    for (int r = 0; r < HALF_ROUNDS; r++) {
        const float4 bX = tbl[(2 * r)     * 32 + lane];
        const float4 bY = tbl[(2 * r + 1) * 32 + lane];
        const float4 L = lab4[r * 4 + tig];

        float cXA[4] = {0,0,0,0}, cYA[4] = {0,0,0,0};
        float cXB[4] = {0,0,0,0}, cYB[4] = {0,0,0,0};
        // 8 MMAs: 2 tiles x 2 k-steps x 2 ray-groups, one B load pair
        mma_tf32(cXA[0], cXA[1], cXA[2], cXA[3],
                 afr[0][0][0], afr[0][0][1], afr[0][0][2], afr[0][0][3],
                 __float_as_uint(bX.x), __float_as_uint(bX.y));
        mma_tf32(cXA[0], cXA[1], cXA[2], cXA[3],
                 afr[1][0][0], afr[1][0][1], afr[1][0][2], afr[1][0][3],
                 __float_as_uint(bX.z), __float_as_uint(bX.w));
        mma_tf32(cXB[0], cXB[1], cXB[2], cXB[3],
                 afr[0][1][0], afr[0][1][1], afr[0][1][2], afr[0][1][3],
                 __float_as_uint(bX.x), __float_as_uint(bX.y));
        mma_tf32(cXB[0], cXB[1], cXB[2], cXB[3],
                 afr[1][1][0], afr[1][1][1], afr[1][1][2], afr[1][1][3],
                 __float_as_uint(bX.z), __float_as_uint(bX.w));
        mma_tf32(cYA[0], cYA[1], cYA[2], cYA[3],
                 afr[0][0][0], afr[0][0][1], afr[0][0][2], afr[0][0][3],
                 __float_as_uint(bY.x), __float_as_uint(bY.y));
        mma_tf32(cYA[0], cYA[1], cYA[2], cYA[3],
                 afr[1][0][0], afr[1][0][1], afr[1][0][2], afr[1][0][3],
                 __float_as_uint(bY.z), __float_as_uint(bY.w));
        mma_tf32(cYB[0], cYB[1], cYB[2], cYB[3],
                 afr[0][1][0], afr[0][1][1], afr[0][1][2], afr[0][1][3],
                 __float_as_uint(bY.x), __float_as_uint(bY.y));
        mma_tf32(cYB[0], cYB[1], cYB[2], cYB[3],
                 afr[1][1][0], afr[1][1][1], afr[1][1][2], afr[1][1][3],
                 __float_as_uint(bY.z), __float_as_uint(bY.w));

        EPI4(cXA, L.x, L.y, aA0, aA1, aA2, aA3)
        EPI4(cYA, L.z, L.w, aA0, aA1, aA2, aA3)
        EPI4(cXB, L.x, L.y, aB0, aB1, aB2, aB3)
        EPI4(cYB, L.z, L.w, aB0, aB1, aB2, aB3)
    }

    float sA_lo = aA0 + aA1, sA_hi = aA2 + aA3;   // rays gid, gid+8
    float sB_lo = aB0 + aB1, sB_hi = aB2 + aB3;   // rays 16+gid, 24+gid

    #pragma unroll
    for (int d = 1; d < 4; d <<= 1) {
        sA_lo += __shfl_xor_sync(0xffffffffu, sA_lo, d);
        sA_hi += __shfl_xor_sync(0xffffffffu, sA_hi, d);
        sB_lo += __shfl_xor_sync(0xffffffffu, sB_lo, d);
        sB_hi += __shfl_xor_sync(0xffffffffu, sB_hi, d);
    }

    // ---- publish half-partials ----
    if (tig == 0) {
        float* dst = g_part + hf * N_RAYS + ray_base;
        dst[gid]      = sA_lo;
        dst[gid + 8]  = sA_hi;
        dst[gid + 16] = sB_lo;
        dst[gid + 24] = sB_hi;
    }
    __syncthreads();

    // ---- threadfence reduction: second arriver combines + sigmoids ----
    volatile int* sflag = reinterpret_cast<volatile int*>(smem_raw + SM_FLAG);
    if (tid == 0) {
        __threadfence();
        int old = atomicAdd(&g_cnt[rg], 1);
        *sflag = (old == 1);
    }
    __syncthreads();

    if (*sflag) {
        __threadfence();
        {
            const int n = rg * RAYS_PER_BLOCK + tid;
            const float s = g_part[n] + g_part[N_RAYS + n];
            const float z = -s * 1.4426950408889634f;
            float em, prob;
            asm("ex2.approx.ftz.f32 %0, %1;" : "=f"(em) : "f"(z));
            asm("rcp.approx.ftz.f32 %0, %1;" : "=f"(prob) : "f"(1.0f + em));
            out[n] = prob;
        }
        __syncthreads();
        if (tid == 0) g_cnt[rg] = 0;   // reset for next graph replay
    }
}

// ---------------------------------------------------------------------------
extern "C" void kernel_launch(void* const* d_in, const int* in_sizes, int n_in,
                              void* d_out, int out_size) {
    const float* origins    = (const float*)d_in[0];
    const float* directions = (const float*)d_in[1];
    const float* means      = (const float*)d_in[2];
    const float* covs       = (const float*)d_in[3];
    const float* labels     = (const float*)d_in[4];
    float* out = (float*)d_out;

    prep_kernel<<<32, 32>>>(means, covs, labels);

    cudaFuncSetAttribute(decoder_kernel,
                         cudaFuncAttributeMaxDynamicSharedMemorySize, SM_TOTAL);

    cudaLaunchConfig_t cfg = {};
    cfg.gridDim  = dim3(2 * NGROUPS, 1, 1);
    cfg.blockDim = dim3(128, 1, 1);
    cfg.dynamicSmemBytes = SM_TOTAL;
    cfg.stream = 0;
    cudaLaunchAttribute attrs[1];
    attrs[0].id = cudaLaunchAttributeProgrammaticStreamSerialization;
    attrs[0].val.programmaticStreamSerializationAllowed = 1;
    cfg.attrs = attrs;
    cfg.numAttrs = 1;
    cudaLaunchKernelEx(&cfg, decoder_kernel, origins, directions, out);
}